// round 1
// baseline (speedup 1.0000x reference)
#include <cuda_runtime.h>

#define Dd   32
#define Nn   256
#define Bb   4
#define Hh   512
#define Kk   256          // H/2
#define TMP_PITCH 33
#define ZJ_PITCH  33

// dynamic smem layout:
//   tmpS : 512*33 floats  (tmp[h][c], padded)
//   zjS  : 256*33 floats  (z[b][j][c], padded)
//   h1S  : 32*512 floats  (h1 tile [j_local][h])
#define SMEM_BYTES ((Hh*TMP_PITCH + Nn*ZJ_PITCH + 32*Hh) * 4)

extern __shared__ float smem[];

__global__ __launch_bounds__(256, 1)
void decoder_fused_kernel(const float* __restrict__ z,
                          const float* __restrict__ motif_mask,
                          const float* __restrict__ W1,
                          const float* __restrict__ b1,
                          const float* __restrict__ W2,
                          const float* __restrict__ b2,
                          const float* __restrict__ W3,
                          const float* __restrict__ b3,
                          float* __restrict__ out)
{
    float* tmpS = smem;                       // 512*33
    float* zjS  = tmpS + Hh * TMP_PITCH;      // 256*33
    float* h1S  = zjS  + Nn * ZJ_PITCH;       // 32*512

    __shared__ float ziS[Dd];
    __shared__ float mmS[Nn];

    const int t  = threadIdx.x;
    const int bi = blockIdx.x;           // b*256 + i
    const int b  = bi >> 8;
    const int i  = bi & 255;

    // ---- stage inputs ----
    if (t < Dd) ziS[t] = z[bi * Dd + t];
    mmS[t] = motif_mask[b * Nn + t];
    for (int idx = t; idx < Nn * Dd; idx += 256) {
        int j = idx >> 5, c = idx & 31;
        zjS[j * ZJ_PITCH + c] = z[(b * Nn + j) * Dd + c];
    }
    __syncthreads();

    // ---- phase 1: tmp[h][c] = sum_a zi[a] * W1[(a*32+c)*512 + h] ----
    // lanes take consecutive h -> coalesced W1 reads.
    for (int r = 0; r < (Hh * Dd) / 256; r++) {
        int idx = t + 256 * r;
        int c = idx >> 9;        // 0..31
        int h = idx & 511;       // 0..511
        float acc = 0.f;
        const float* w1p = W1 + (size_t)c * Hh + h;   // + a*32*512 per step
        #pragma unroll 8
        for (int a = 0; a < Dd; a++)
            acc += ziS[a] * w1p[(size_t)a * Dd * Hh];
        tmpS[h * TMP_PITCH + c] = acc;
    }
    __syncthreads();

    const int warp = t >> 5;     // 0..7
    const int lane = t & 31;
    const float mi = mmS[i];
    const float b3v = b3[0];

    // preload per-thread b2 / W3 (k = lane*8 + e)
    float b2r[8], w3r[8];
    #pragma unroll
    for (int e = 0; e < 8; e++) {
        b2r[e] = b2[lane * 8 + e];
        w3r[e] = W3[lane * 8 + e];
    }

    const float4* W2v = (const float4*)W2;   // W2[h*256 + k] -> float4 idx h*64 + lane*2

    for (int jt0 = 0; jt0 < Nn; jt0 += 32) {
        // ---- h1 tile: j_local = warp*4 + q, h = lane + 32*p ----
        {
            float acc[4][16];
            #pragma unroll
            for (int q = 0; q < 4; q++)
                #pragma unroll
                for (int p = 0; p < 16; p++) acc[q][p] = 0.f;

            #pragma unroll 4
            for (int c = 0; c < Dd; c++) {
                float zq[4];
                #pragma unroll
                for (int q = 0; q < 4; q++)
                    zq[q] = zjS[(jt0 + warp * 4 + q) * ZJ_PITCH + c];   // broadcast
                #pragma unroll
                for (int p = 0; p < 16; p++) {
                    float tv = tmpS[(lane + 32 * p) * TMP_PITCH + c];   // conflict-free
                    #pragma unroll
                    for (int q = 0; q < 4; q++)
                        acc[q][p] += zq[q] * tv;
                }
            }
            #pragma unroll
            for (int q = 0; q < 4; q++)
                #pragma unroll
                for (int p = 0; p < 16; p++) {
                    int h = lane + 32 * p;
                    float v = acc[q][p] + b1[h];
                    h1S[(warp * 4 + q) * Hh + h] = fmaxf(v, 0.f);
                }
        }
        __syncthreads();

        // ---- h2: acc2[q][e] = sum_h h1[j][h] * W2[h][lane*8+e] ----
        float acc2[4][8];
        #pragma unroll
        for (int q = 0; q < 4; q++)
            #pragma unroll
            for (int e = 0; e < 8; e++) acc2[q][e] = 0.f;

        #pragma unroll 2
        for (int h = 0; h < Hh; h++) {
            float a4[4];
            #pragma unroll
            for (int q = 0; q < 4; q++)
                a4[q] = h1S[(warp * 4 + q) * Hh + h];                  // broadcast
            float4 w0 = W2v[h * 64 + lane * 2];
            float4 w1 = W2v[h * 64 + lane * 2 + 1];
            #pragma unroll
            for (int q = 0; q < 4; q++) {
                acc2[q][0] += a4[q] * w0.x;  acc2[q][1] += a4[q] * w0.y;
                acc2[q][2] += a4[q] * w0.z;  acc2[q][3] += a4[q] * w0.w;
                acc2[q][4] += a4[q] * w1.x;  acc2[q][5] += a4[q] * w1.y;
                acc2[q][6] += a4[q] * w1.z;  acc2[q][7] += a4[q] * w1.w;
            }
        }

        // ---- relu + b2, dot W3, warp reduction over k ----
        float part[4];
        #pragma unroll
        for (int q = 0; q < 4; q++) {
            float s = 0.f;
            #pragma unroll
            for (int e = 0; e < 8; e++) {
                float v = fmaxf(acc2[q][e] + b2r[e], 0.f);
                s += v * w3r[e];
            }
            part[q] = s;
        }
        #pragma unroll
        for (int off = 16; off > 0; off >>= 1)
            #pragma unroll
            for (int q = 0; q < 4; q++)
                part[q] += __shfl_down_sync(0xffffffffu, part[q], off);

        if (lane == 0) {
            #pragma unroll
            for (int q = 0; q < 4; q++) {
                int j = jt0 + warp * 4 + q;
                float lg = (part[q] + b3v) * mi * mmS[j];
                size_t o = ((size_t)bi) * Nn + j;
                // out = [contact_map | contact_logits]
                out[o] = 1.f / (1.f + __expf(-lg));
                out[(size_t)Bb * Nn * Nn + o] = lg;
            }
        }
        __syncthreads();   // protect h1S before next tile overwrites it
    }
}

extern "C" void kernel_launch(void* const* d_in, const int* in_sizes, int n_in,
                              void* d_out, int out_size)
{
    const float* z   = (const float*)d_in[0];
    const float* mm  = (const float*)d_in[1];
    // d_in[2] = residue_mask (unused by reference)
    const float* W1  = (const float*)d_in[3];
    const float* b1  = (const float*)d_in[4];
    const float* W2  = (const float*)d_in[5];
    const float* b2  = (const float*)d_in[6];
    const float* W3  = (const float*)d_in[7];
    const float* b3  = (const float*)d_in[8];
    float* out = (float*)d_out;

    cudaFuncSetAttribute(decoder_fused_kernel,
                         cudaFuncAttributeMaxDynamicSharedMemorySize, SMEM_BYTES);

    decoder_fused_kernel<<<Bb * Nn, 256, SMEM_BYTES>>>(
        z, mm, W1, b1, W2, b2, W3, b3, out);
}